// round 16
// baseline (speedup 1.0000x reference)
#include <cuda_runtime.h>
#include <cuda_bf16.h>
#include <math.h>

#define B_ 64
#define S_ 512
#define I_ 256
#define H_ 1024
#define O_ 256

__device__ float g_buf0[S_ * B_ * H_];
__device__ float g_buf1[S_ * B_ * H_];
__device__ int g_flags[2 * S_ * 16];
__device__ __nv_bfloat16 g_ahi[S_ * B_ * H_];
__device__ __nv_bfloat16 g_alo[S_ * B_ * H_];
__device__ __nv_bfloat16 g_bhi[H_ * H_];
__device__ __nv_bfloat16 g_blo[H_ * H_];
__device__ __nv_bfloat16 g_whi[H_ * H_];
__device__ __nv_bfloat16 g_wlo[H_ * H_];

typedef unsigned long long u64;
typedef unsigned int u32;

__device__ __forceinline__ void cpasync16r(unsigned sdst, const void* gsrc) {
    asm volatile("cp.async.cg.shared.global [%0], [%1], 16;" :: "r"(sdst), "l"(gsrc));
}
__device__ __forceinline__ int ld_acq(const int* p) {
    int v; asm volatile("ld.acquire.gpu.global.b32 %0, [%1];" : "=r"(v) : "l"(p) : "memory");
    return v;
}
__device__ __forceinline__ void red_release(int* p) {
    asm volatile("red.release.gpu.global.add.s32 [%0], 1;" :: "l"(p) : "memory");
}
__device__ __forceinline__ unsigned smem_u32(const void* p) {
    unsigned a; asm("{ .reg .u64 t; cvta.to.shared.u64 t, %1; cvt.u32.u64 %0, t; }" : "=r"(a) : "l"(p));
    return a;
}
__device__ __forceinline__ u32 splitpk(float x, float y, u32& lo) {
    __nv_bfloat16 hx = __float2bfloat16(x), hy = __float2bfloat16(y);
    __nv_bfloat16 lx = __float2bfloat16(x - __bfloat162float(hx));
    __nv_bfloat16 ly = __float2bfloat16(y - __bfloat162float(hy));
    lo = ((u32)__bfloat16_as_ushort(ly) << 16) | __bfloat16_as_ushort(lx);
    return ((u32)__bfloat16_as_ushort(hy) << 16) | __bfloat16_as_ushort(hx);
}

__global__ void zero_flags_k(int* f) { f[blockIdx.x * 1024 + threadIdx.x] = 0; }

__global__ void __launch_bounds__(256) split_k(const float* __restrict__ src,
                                               __nv_bfloat16* __restrict__ hi,
                                               __nv_bfloat16* __restrict__ lo) {
    int i = blockIdx.x * 256 + threadIdx.x;
    float4 v = __ldg((const float4*)src + i);
    u32 h0, h1, l0, l1;
    h0 = splitpk(v.x, v.y, l0);
    h1 = splitpk(v.z, v.w, l1);
    ((uint2*)hi)[i] = make_uint2(h0, h1);
    ((uint2*)lo)[i] = make_uint2(l0, l1);
}

// ---------------------------------------------------------------------------
// Split-bf16 mma.sync GEMM (validated R13-R15). 128x64 tile, 8 warps, 3-stage.
// ---------------------------------------------------------------------------
#define LDSM4(R, ADDR) asm volatile( \
    "ldmatrix.sync.aligned.m8n8.x4.shared.b16 {%0,%1,%2,%3}, [%4];" \
    : "=r"((R)[0]), "=r"((R)[1]), "=r"((R)[2]), "=r"((R)[3]) : "r"(ADDR))
#define LDSM2(R, ADDR) asm volatile( \
    "ldmatrix.sync.aligned.m8n8.x2.shared.b16 {%0,%1}, [%2];" \
    : "=r"((R)[0]), "=r"((R)[1]) : "r"(ADDR))
#define MMA16816(D, A, B0, B1) asm volatile( \
    "mma.sync.aligned.m16n8k16.row.col.f32.bf16.bf16.f32 " \
    "{%0,%1,%2,%3}, {%4,%5,%6,%7}, {%8,%9}, {%0,%1,%2,%3};" \
    : "+f"((D)[0]), "+f"((D)[1]), "+f"((D)[2]), "+f"((D)[3]) \
    : "r"((A)[0]), "r"((A)[1]), "r"((A)[2]), "r"((A)[3]), "r"(B0), "r"(B1))

#define STG_H 15360

template <int K, int CROW, int HASB2>
__global__ void __launch_bounds__(256) mgemm_k(const __nv_bfloat16* __restrict__ Ahi,
                                               const __nv_bfloat16* __restrict__ Alo,
                                               const __nv_bfloat16* __restrict__ Bhi,
                                               const __nv_bfloat16* __restrict__ Blo,
                                               const float* __restrict__ b1,
                                               const float* __restrict__ b2,
                                               float* __restrict__ C) {
    extern __shared__ __nv_bfloat16 sm[];
    const unsigned smb = smem_u32(sm);
    const int tid = threadIdx.x, lane = tid & 31, warp = tid >> 5;
    const int wm = warp >> 1, wn = warp & 1;
    const int m0 = blockIdx.y * 128, n0g = blockIdx.x * 64;

    float acc[2][4][4];
#pragma unroll
    for (int i = 0; i < 2; i++)
#pragma unroll
        for (int j = 0; j < 4; j++)
#pragma unroll
            for (int e = 0; e < 4; e++) acc[i][j][e] = 0.0f;

#define ISSUE(CC)                                                              \
    { int kc_ = (CC) * 32; unsigned sg_ = ((CC) % 3) * STG_H;                  \
      _Pragma("unroll") for (int i_ = 0; i_ < 2; i_++) {                       \
          int v_ = tid + i_ * 256, r_ = v_ >> 2, c4_ = v_ & 3;                 \
          cpasync16r(smb + (sg_ + r_ * 40 + c4_ * 8) * 2,                      \
                     Ahi + (size_t)(m0 + r_) * K + kc_ + c4_ * 8);             \
          cpasync16r(smb + (sg_ + 5120 + r_ * 40 + c4_ * 8) * 2,               \
                     Alo + (size_t)(m0 + r_) * K + kc_ + c4_ * 8);             \
      }                                                                        \
      { int r_ = tid >> 2, c4_ = tid & 3;                                      \
        cpasync16r(smb + (sg_ + 10240 + r_ * 40 + c4_ * 8) * 2,                \
                   Bhi + (size_t)(n0g + r_) * K + kc_ + c4_ * 8);              \
        cpasync16r(smb + (sg_ + 12800 + r_ * 40 + c4_ * 8) * 2,                \
                   Blo + (size_t)(n0g + r_) * K + kc_ + c4_ * 8);              \
      }                                                                        \
      asm volatile("cp.async.commit_group;"); }

    const int NCH = K / 32;
    ISSUE(0)
    ISSUE(1)
    ISSUE(2)
    for (int c = 0; c < NCH; c++) {
        if (c + 2 < NCH)      asm volatile("cp.async.wait_group 2;" ::: "memory");
        else if (c + 1 < NCH) asm volatile("cp.async.wait_group 1;" ::: "memory");
        else                  asm volatile("cp.async.wait_group 0;" ::: "memory");
        __syncthreads();
        const unsigned sg = (c % 3) * STG_H;
        const unsigned ah = smb + sg * 2;
        const unsigned al = smb + (sg + 5120) * 2;
        const unsigned wh = smb + (sg + 10240) * 2;
        const unsigned wl = smb + (sg + 12800) * 2;
        const int arow = wm * 32 + (lane & 7) + ((lane & 8) ? 8 : 0);
        const int acolx = (lane & 16) ? 8 : 0;
        const int brow = wn * 32 + (lane & 7);
        const int bcolx = (lane & 8) ? 8 : 0;
#pragma unroll
        for (int ks = 0; ks < 2; ks++) {
            u32 a_h[2][4], a_l[2][4], b_h[4][2], b_l[4][2];
#pragma unroll
            for (int mi = 0; mi < 2; mi++) {
                unsigned off = ((arow + mi * 16) * 40 + ks * 16 + acolx) * 2;
                LDSM4(a_h[mi], ah + off);
                LDSM4(a_l[mi], al + off);
            }
#pragma unroll
            for (int ni = 0; ni < 4; ni++) {
                unsigned off = ((brow + ni * 8) * 40 + ks * 16 + bcolx) * 2;
                LDSM2(b_h[ni], wh + off);
                LDSM2(b_l[ni], wl + off);
            }
#pragma unroll
            for (int mi = 0; mi < 2; mi++)
#pragma unroll
                for (int ni = 0; ni < 4; ni++) {
                    MMA16816(acc[mi][ni], a_h[mi], b_h[ni][0], b_h[ni][1]);
                    MMA16816(acc[mi][ni], a_h[mi], b_l[ni][0], b_l[ni][1]);
                    MMA16816(acc[mi][ni], a_l[mi], b_h[ni][0], b_h[ni][1]);
                }
        }
        __syncthreads();
        if (c + 3 < NCH) ISSUE(c + 3)
    }
#undef ISSUE

    const int NCW = (CROW == 1) ? O_ : H_;
#pragma unroll
    for (int mi = 0; mi < 2; mi++) {
        int m = m0 + wm * 32 + mi * 16 + (lane >> 2);
        int mB = m + 8;
        size_t r0, r1;
        if (CROW == 1)      { r0 = (size_t)(m & 63) * S_ + (m >> 6);  r1 = (size_t)(mB & 63) * S_ + (mB >> 6); }
        else if (CROW == 2) { r0 = (size_t)(m % S_) * 64 + (m / S_);  r1 = (size_t)(mB % S_) * 64 + (mB / S_); }
        else                { r0 = (size_t)m;                          r1 = (size_t)mB; }
#pragma unroll
        for (int ni = 0; ni < 4; ni++) {
            int n = n0g + wn * 32 + ni * 8 + (lane & 3) * 2;
            float bv0 = __ldg(b1 + n) + (HASB2 ? __ldg(b2 + n) : 0.0f);
            float bv1 = __ldg(b1 + n + 1) + (HASB2 ? __ldg(b2 + n + 1) : 0.0f);
            *(float2*)(C + r0 * NCW + n) = make_float2(acc[mi][ni][0] + bv0, acc[mi][ni][1] + bv1);
            *(float2*)(C + r1 * NCW + n) = make_float2(acc[mi][ni][2] + bv0, acc[mi][ni][3] + bv1);
        }
    }
}

// ---------------------------------------------------------------------------
// Dual-chain warp-specialized tensor-core recurrence.
// grid 128: bp = blockIdx&1 (b pair), ng = blockIdx>>1 (0..63), n0 = ng*16.
// Chain = warp>>2 (A: warps 0-3, B: 4-7), bg = bp*2+chain, b0 = bp*32+chain*16.
// Within chain: warp cw = warp&3 owns k-chunk [cw*256, cw*256+256).
// W slice (16n x 1024k, hi+lo, rows stride 1032 halves) shared by chains.
// Per chain-step: prefetch pre tile; poll flag (target 64 = 16 CTAs x 4 warps);
// warp copies own h chunk (hi+lo), wait_all + syncwarp (self-owned data);
// mma 16 ks x (2 LDSM4 A + 2 LDSM4 B + 6 MMA); red partials; chain barrier;
// finalize (sum + pre + tanh + re-split, u32 stores); per-warp release;
// chain barrier (red reuse). Chains never share a barrier -> true overlap.
// ---------------------------------------------------------------------------
#define oWlo 33024u
#define oHch 66048u          // + chain*66048 : [Hhi 33024 | Hlo 33024]
#define oRed 198144u         // + chain*4096  : [4][16][16] f32
#define oPre 206336u         // + chain*1024  : [16][16] f32
#define RNN_SMEM 208384

__global__ void __launch_bounds__(256) rnn_mma_k(const __nv_bfloat16* __restrict__ Whi,
                                                 const __nv_bfloat16* __restrict__ Wlo,
                                                 const float* __restrict__ pre,
                                                 __nv_bfloat16* Hhi,
                                                 __nv_bfloat16* Hlo,
                                                 int* __restrict__ flags) {
    extern __shared__ __align__(16) char sch[];
    const unsigned smb = smem_u32(sch);
    const int tid = threadIdx.x, lane = tid & 31, warp = tid >> 5;
    const int chain = warp >> 2, cw = warp & 3;
    const int bp = blockIdx.x & 1, ng = blockIdx.x >> 1;
    const int n0 = ng * 16;
    const int bg = bp * 2 + chain;
    const int b0 = bp * 32 + chain * 16;
    const int mychunk = ng >> 4;
    const int ctid = tid & 127;
    const int barid = 1 + chain;

    // Load W slice (hi+lo): 16 rows x 1024 halves each
    for (int i = tid; i < 2048; i += 256) {
        int r = i >> 7, c = i & 127;
        cpasync16r(smb + (r * 1032 + c * 8) * 2, Whi + (size_t)(n0 + r) * H_ + c * 8);
        cpasync16r(smb + oWlo + (r * 1032 + c * 8) * 2, Wlo + (size_t)(n0 + r) * H_ + c * 8);
    }
    asm volatile("cp.async.wait_all;" ::: "memory");

    // t = 0: h_0 = tanh(pre_0) for both chains' tiles (full CTA)
    {
        int ch = tid >> 7, b = (tid >> 3) & 15, P = tid & 7;
        int bb = bp * 32 + ch * 16 + b;
        float2 v = *(const float2*)(pre + (size_t)bb * H_ + n0 + P * 2);
        u32 lo, hi = splitpk(tanhf(v.x), tanhf(v.y), lo);
        size_t o = (size_t)bb * H_ + n0 + P * 2;
        *(u32*)(Hhi + o) = hi;
        *(u32*)(Hlo + o) = lo;
    }
    __syncthreads();
    if (lane == 0) red_release(&flags[0 * 16 + bg * 4 + mychunk]);

    const unsigned sHhi = smb + oHch + chain * 66048u;
    const unsigned sHlo = sHhi + 33024u;
    float* redc = (float*)(sch + oRed + chain * 4096u);
    float* prec = (float*)(sch + oPre + chain * 1024u);

    const int arow = (lane & 7) + ((lane & 8) ? 8 : 0);
    const int acolx = (lane & 16) ? 8 : 0;
    const int brow = (lane & 7) + ((lane & 16) ? 8 : 0);
    const int bcolx = (lane & 8) ? 8 : 0;

    for (int t = 1; t < S_; t++) {
        // prefetch pre_t tile (16b x 16n f32, 1KB) by first 64 threads of chain
        if (ctid < 64) {
            int r = ctid >> 2, c = (ctid & 3) * 4;
            cpasync16r(smb + oPre + chain * 1024u + (r * 16 + c) * 4,
                       pre + ((size_t)t * B_ + b0 + r) * H_ + n0 + c);
        }
        // poll this warp's k-chunk flag
        {
            const int* fl = &flags[(t - 1) * 16 + bg * 4 + cw];
            while (ld_acq(fl) < 64) { }
        }
        // copy own h chunk (16 rows x 256 halves, hi+lo)
        {
            const __nv_bfloat16* gh = Hhi + ((size_t)(t - 1) * B_ + b0) * H_ + cw * 256;
            const __nv_bfloat16* gl = Hlo + ((size_t)(t - 1) * B_ + b0) * H_ + cw * 256;
#pragma unroll
            for (int i = 0; i < 16; i++) {
                int v = lane + i * 32, r = v >> 5, c = v & 31;
                unsigned so = (r * 1032 + cw * 256 + c * 8) * 2;
                cpasync16r(sHhi + so, gh + (size_t)r * H_ + c * 8);
                cpasync16r(sHlo + so, gl + (size_t)r * H_ + c * 8);
            }
            asm volatile("cp.async.wait_all;" ::: "memory");
            __syncwarp();
        }

        // compute: 16b x 16n x 256k per warp
        float c0[4] = {0, 0, 0, 0}, c1[4] = {0, 0, 0, 0};
#pragma unroll
        for (int ks = 0; ks < 16; ks++) {
            const int kk = cw * 256 + ks * 16;
            u32 ah[4], al[4], bh[4], bl[4];
            unsigned aoff = (arow * 1032 + kk + acolx) * 2;
            LDSM4(ah, sHhi + aoff);
            LDSM4(al, sHlo + aoff);
            unsigned boff = (brow * 1032 + kk + bcolx) * 2;
            LDSM4(bh, smb + boff);
            LDSM4(bl, smb + oWlo + boff);
            MMA16816(c0, ah, bh[0], bh[1]);
            MMA16816(c0, ah, bl[0], bl[1]);
            MMA16816(c0, al, bh[0], bh[1]);
            MMA16816(c1, ah, bh[2], bh[3]);
            MMA16816(c1, ah, bl[2], bl[3]);
            MMA16816(c1, al, bh[2], bh[3]);
        }
        // write kg partials: red[cw][b16][n16]
        {
            int rb = lane >> 2, nb = (lane & 3) * 2;
            float* rw = redc + (cw * 16 + rb) * 16;
            rw[nb] = c0[0];       rw[nb + 1] = c0[1];
            rw[nb + 8] = c1[0];   rw[nb + 9] = c1[1];
            rw += 8 * 16;
            rw[nb] = c0[2];       rw[nb + 1] = c0[3];
            rw[nb + 8] = c1[2];   rw[nb + 9] = c1[3];
        }
        asm volatile("bar.sync %0, 128;" :: "r"(barid) : "memory");

        // finalize: thread -> (b, n-pair)
        {
            int b = ctid >> 3, P = ctid & 7;
            float sx = 0.f, sy = 0.f;
#pragma unroll
            for (int g = 0; g < 4; g++) {
                sx += redc[(g * 16 + b) * 16 + P * 2];
                sy += redc[(g * 16 + b) * 16 + P * 2 + 1];
            }
            float2 pv = *(const float2*)(prec + b * 16 + P * 2);
            u32 lo, hi = splitpk(tanhf(sx + pv.x), tanhf(sy + pv.y), lo);
            size_t o = ((size_t)t * B_ + b0 + b) * H_ + n0 + P * 2;
            *(u32*)(Hhi + o) = hi;
            *(u32*)(Hlo + o) = lo;
        }
        __syncwarp();
        if (lane == 0) red_release(&flags[t * 16 + bg * 4 + mychunk]);
        asm volatile("bar.sync %0, 128;" :: "r"(barid) : "memory");   // red reuse
    }
}

// ---------------------------------------------------------------------------

extern "C" void kernel_launch(void* const* d_in, const int* in_sizes, int n_in,
                              void* d_out, int out_size) {
    const float* x      = (const float*)d_in[0];
    const float* W_ih_0 = (const float*)d_in[1];
    const float* W_hh_0 = (const float*)d_in[2];
    const float* b_ih_0 = (const float*)d_in[3];
    const float* b_hh_0 = (const float*)d_in[4];
    const float* W_ih_1 = (const float*)d_in[5];
    const float* W_hh_1 = (const float*)d_in[6];
    const float* b_ih_1 = (const float*)d_in[7];
    const float* b_hh_1 = (const float*)d_in[8];
    const float* fc_w   = (const float*)d_in[9];
    const float* fc_b   = (const float*)d_in[10];
    float* out = (float*)d_out;

    float *buf0, *buf1;
    int* flags;
    __nv_bfloat16 *ahi, *alo, *bhi, *blo, *whi, *wlo;
    cudaGetSymbolAddress((void**)&buf0, g_buf0);
    cudaGetSymbolAddress((void**)&buf1, g_buf1);
    cudaGetSymbolAddress((void**)&flags, g_flags);
    cudaGetSymbolAddress((void**)&ahi, g_ahi);
    cudaGetSymbolAddress((void**)&alo, g_alo);
    cudaGetSymbolAddress((void**)&bhi, g_bhi);
    cudaGetSymbolAddress((void**)&blo, g_blo);
    cudaGetSymbolAddress((void**)&whi, g_whi);
    cudaGetSymbolAddress((void**)&wlo, g_wlo);

    const int mg_smem = 3 * STG_H * 2;   // 92160 B
    static bool attr_set = false;
    if (!attr_set) {
        cudaFuncSetAttribute(rnn_mma_k, cudaFuncAttributeMaxDynamicSharedMemorySize, RNN_SMEM);
        cudaFuncSetAttribute(mgemm_k<I_, 2, 1>, cudaFuncAttributeMaxDynamicSharedMemorySize, mg_smem);
        cudaFuncSetAttribute(mgemm_k<H_, 0, 1>, cudaFuncAttributeMaxDynamicSharedMemorySize, mg_smem);
        cudaFuncSetAttribute(mgemm_k<H_, 1, 0>, cudaFuncAttributeMaxDynamicSharedMemorySize, mg_smem);
        attr_set = true;
    }

    zero_flags_k<<<16, 1024>>>(flags);
    // pre0: split x and W_ih_0, tensor GEMM into buf0 [s][b][h]
    split_k<<<(B_ * S_ * I_ / 4) / 256, 256>>>(x, ahi, alo);
    split_k<<<(H_ * I_ / 4) / 256, 256>>>(W_ih_0, bhi, blo);
    mgemm_k<I_, 2, 1><<<dim3(H_ / 64, (B_ * S_) / 128), 256, mg_smem>>>(
        ahi, alo, bhi, blo, b_ih_0, b_hh_0, buf0);
    // L0 recurrence (writes h0 hi/lo into ahi/alo)
    split_k<<<(H_ * H_ / 4) / 256, 256>>>(W_hh_0, whi, wlo);
    rnn_mma_k<<<128, 256, RNN_SMEM>>>(whi, wlo, buf0, ahi, alo, flags);
    // pre1 = h0 @ W1_ih^T + biases (h0 already split)
    split_k<<<(H_ * H_ / 4) / 256, 256>>>(W_ih_1, bhi, blo);
    mgemm_k<H_, 0, 1><<<dim3(H_ / 64, (S_ * B_) / 128), 256, mg_smem>>>(
        ahi, alo, bhi, blo, b_ih_1, b_hh_1, buf1);
    // L1 recurrence (writes h1 hi/lo into ahi/alo)
    split_k<<<(H_ * H_ / 4) / 256, 256>>>(W_hh_1, whi, wlo);
    rnn_mma_k<<<128, 256, RNN_SMEM>>>(whi, wlo, buf1, ahi, alo, flags + S_ * 16);
    // fc (h1 already split)
    split_k<<<(O_ * H_ / 4) / 256, 256>>>(fc_w, bhi, blo);
    mgemm_k<H_, 1, 0><<<dim3(O_ / 64, (S_ * B_) / 128), 256, mg_smem>>>(
        ahi, alo, bhi, blo, fc_b, nullptr, out);
}

// round 17
// speedup vs baseline: 1.1273x; 1.1273x over previous
#include <cuda_runtime.h>
#include <cuda_bf16.h>
#include <math.h>

#define B_ 64
#define S_ 512
#define I_ 256
#define H_ 1024
#define O_ 256

__device__ float g_buf0[S_ * B_ * H_];
__device__ float g_buf1[S_ * B_ * H_];
__device__ int g_flags[2 * S_ * 16];
__device__ __nv_bfloat16 g_ahi[S_ * B_ * H_];
__device__ __nv_bfloat16 g_alo[S_ * B_ * H_];
__device__ __nv_bfloat16 g_bhi[H_ * H_];
__device__ __nv_bfloat16 g_blo[H_ * H_];
__device__ __nv_bfloat16 g_whi[H_ * H_];
__device__ __nv_bfloat16 g_wlo[H_ * H_];

typedef unsigned long long u64;
typedef unsigned int u32;

__device__ __forceinline__ void cpasync16r(unsigned sdst, const void* gsrc) {
    asm volatile("cp.async.cg.shared.global [%0], [%1], 16;" :: "r"(sdst), "l"(gsrc));
}
__device__ __forceinline__ int ld_acq(const int* p) {
    int v; asm volatile("ld.acquire.gpu.global.b32 %0, [%1];" : "=r"(v) : "l"(p) : "memory");
    return v;
}
__device__ __forceinline__ void red_release(int* p) {
    asm volatile("red.release.gpu.global.add.s32 [%0], 1;" :: "l"(p) : "memory");
}
__device__ __forceinline__ unsigned smem_u32(const void* p) {
    unsigned a; asm("{ .reg .u64 t; cvta.to.shared.u64 t, %1; cvt.u32.u64 %0, t; }" : "=r"(a) : "l"(p));
    return a;
}
__device__ __forceinline__ u32 splitpk(float x, float y, u32& lo) {
    __nv_bfloat16 hx = __float2bfloat16(x), hy = __float2bfloat16(y);
    __nv_bfloat16 lx = __float2bfloat16(x - __bfloat162float(hx));
    __nv_bfloat16 ly = __float2bfloat16(y - __bfloat162float(hy));
    lo = ((u32)__bfloat16_as_ushort(ly) << 16) | __bfloat16_as_ushort(lx);
    return ((u32)__bfloat16_as_ushort(hy) << 16) | __bfloat16_as_ushort(hx);
}

__global__ void zero_flags_k(int* f) { f[blockIdx.x * 1024 + threadIdx.x] = 0; }

__global__ void __launch_bounds__(256) split_k(const float* __restrict__ src,
                                               __nv_bfloat16* __restrict__ hi,
                                               __nv_bfloat16* __restrict__ lo) {
    int i = blockIdx.x * 256 + threadIdx.x;
    float4 v = __ldg((const float4*)src + i);
    u32 h0, h1, l0, l1;
    h0 = splitpk(v.x, v.y, l0);
    h1 = splitpk(v.z, v.w, l1);
    ((uint2*)hi)[i] = make_uint2(h0, h1);
    ((uint2*)lo)[i] = make_uint2(l0, l1);
}

// ---------------------------------------------------------------------------
// Split-bf16 mma.sync GEMM (validated R13-R15). 128x64 tile, 8 warps, 3-stage.
// ---------------------------------------------------------------------------
#define LDSM4(R, ADDR) asm volatile( \
    "ldmatrix.sync.aligned.m8n8.x4.shared.b16 {%0,%1,%2,%3}, [%4];" \
    : "=r"((R)[0]), "=r"((R)[1]), "=r"((R)[2]), "=r"((R)[3]) : "r"(ADDR))
#define LDSM2(R, ADDR) asm volatile( \
    "ldmatrix.sync.aligned.m8n8.x2.shared.b16 {%0,%1}, [%2];" \
    : "=r"((R)[0]), "=r"((R)[1]) : "r"(ADDR))
#define MMA16816(D, A, B0, B1) asm volatile( \
    "mma.sync.aligned.m16n8k16.row.col.f32.bf16.bf16.f32 " \
    "{%0,%1,%2,%3}, {%4,%5,%6,%7}, {%8,%9}, {%0,%1,%2,%3};" \
    : "+f"((D)[0]), "+f"((D)[1]), "+f"((D)[2]), "+f"((D)[3]) \
    : "r"((A)[0]), "r"((A)[1]), "r"((A)[2]), "r"((A)[3]), "r"(B0), "r"(B1))

#define STG_H 15360

template <int K, int CROW, int HASB2>
__global__ void __launch_bounds__(256) mgemm_k(const __nv_bfloat16* __restrict__ Ahi,
                                               const __nv_bfloat16* __restrict__ Alo,
                                               const __nv_bfloat16* __restrict__ Bhi,
                                               const __nv_bfloat16* __restrict__ Blo,
                                               const float* __restrict__ b1,
                                               const float* __restrict__ b2,
                                               float* __restrict__ C) {
    extern __shared__ __nv_bfloat16 sm[];
    const unsigned smb = smem_u32(sm);
    const int tid = threadIdx.x, lane = tid & 31, warp = tid >> 5;
    const int wm = warp >> 1, wn = warp & 1;
    const int m0 = blockIdx.y * 128, n0g = blockIdx.x * 64;

    float acc[2][4][4];
#pragma unroll
    for (int i = 0; i < 2; i++)
#pragma unroll
        for (int j = 0; j < 4; j++)
#pragma unroll
            for (int e = 0; e < 4; e++) acc[i][j][e] = 0.0f;

#define ISSUE(CC)                                                              \
    { int kc_ = (CC) * 32; unsigned sg_ = ((CC) % 3) * STG_H;                  \
      _Pragma("unroll") for (int i_ = 0; i_ < 2; i_++) {                       \
          int v_ = tid + i_ * 256, r_ = v_ >> 2, c4_ = v_ & 3;                 \
          cpasync16r(smb + (sg_ + r_ * 40 + c4_ * 8) * 2,                      \
                     Ahi + (size_t)(m0 + r_) * K + kc_ + c4_ * 8);             \
          cpasync16r(smb + (sg_ + 5120 + r_ * 40 + c4_ * 8) * 2,               \
                     Alo + (size_t)(m0 + r_) * K + kc_ + c4_ * 8);             \
      }                                                                        \
      { int r_ = tid >> 2, c4_ = tid & 3;                                      \
        cpasync16r(smb + (sg_ + 10240 + r_ * 40 + c4_ * 8) * 2,                \
                   Bhi + (size_t)(n0g + r_) * K + kc_ + c4_ * 8);              \
        cpasync16r(smb + (sg_ + 12800 + r_ * 40 + c4_ * 8) * 2,                \
                   Blo + (size_t)(n0g + r_) * K + kc_ + c4_ * 8);              \
      }                                                                        \
      asm volatile("cp.async.commit_group;"); }

    const int NCH = K / 32;
    ISSUE(0)
    ISSUE(1)
    ISSUE(2)
    for (int c = 0; c < NCH; c++) {
        if (c + 2 < NCH)      asm volatile("cp.async.wait_group 2;" ::: "memory");
        else if (c + 1 < NCH) asm volatile("cp.async.wait_group 1;" ::: "memory");
        else                  asm volatile("cp.async.wait_group 0;" ::: "memory");
        __syncthreads();
        const unsigned sg = (c % 3) * STG_H;
        const unsigned ah = smb + sg * 2;
        const unsigned al = smb + (sg + 5120) * 2;
        const unsigned wh = smb + (sg + 10240) * 2;
        const unsigned wl = smb + (sg + 12800) * 2;
        const int arow = wm * 32 + (lane & 7) + ((lane & 8) ? 8 : 0);
        const int acolx = (lane & 16) ? 8 : 0;
        const int brow = wn * 32 + (lane & 7);
        const int bcolx = (lane & 8) ? 8 : 0;
#pragma unroll
        for (int ks = 0; ks < 2; ks++) {
            u32 a_h[2][4], a_l[2][4], b_h[4][2], b_l[4][2];
#pragma unroll
            for (int mi = 0; mi < 2; mi++) {
                unsigned off = ((arow + mi * 16) * 40 + ks * 16 + acolx) * 2;
                LDSM4(a_h[mi], ah + off);
                LDSM4(a_l[mi], al + off);
            }
#pragma unroll
            for (int ni = 0; ni < 4; ni++) {
                unsigned off = ((brow + ni * 8) * 40 + ks * 16 + bcolx) * 2;
                LDSM2(b_h[ni], wh + off);
                LDSM2(b_l[ni], wl + off);
            }
#pragma unroll
            for (int mi = 0; mi < 2; mi++)
#pragma unroll
                for (int ni = 0; ni < 4; ni++) {
                    MMA16816(acc[mi][ni], a_h[mi], b_h[ni][0], b_h[ni][1]);
                    MMA16816(acc[mi][ni], a_h[mi], b_l[ni][0], b_l[ni][1]);
                    MMA16816(acc[mi][ni], a_l[mi], b_h[ni][0], b_h[ni][1]);
                }
        }
        __syncthreads();
        if (c + 3 < NCH) ISSUE(c + 3)
    }
#undef ISSUE

    const int NCW = (CROW == 1) ? O_ : H_;
#pragma unroll
    for (int mi = 0; mi < 2; mi++) {
        int m = m0 + wm * 32 + mi * 16 + (lane >> 2);
        int mB = m + 8;
        size_t r0, r1;
        if (CROW == 1)      { r0 = (size_t)(m & 63) * S_ + (m >> 6);  r1 = (size_t)(mB & 63) * S_ + (mB >> 6); }
        else if (CROW == 2) { r0 = (size_t)(m % S_) * 64 + (m / S_);  r1 = (size_t)(mB % S_) * 64 + (mB / S_); }
        else                { r0 = (size_t)m;                          r1 = (size_t)mB; }
#pragma unroll
        for (int ni = 0; ni < 4; ni++) {
            int n = n0g + wn * 32 + ni * 8 + (lane & 3) * 2;
            float bv0 = __ldg(b1 + n) + (HASB2 ? __ldg(b2 + n) : 0.0f);
            float bv1 = __ldg(b1 + n + 1) + (HASB2 ? __ldg(b2 + n + 1) : 0.0f);
            *(float2*)(C + r0 * NCW + n) = make_float2(acc[mi][ni][0] + bv0, acc[mi][ni][1] + bv1);
            *(float2*)(C + r1 * NCW + n) = make_float2(acc[mi][ni][2] + bv0, acc[mi][ni][3] + bv1);
        }
    }
}

// ---------------------------------------------------------------------------
// Tensor-core recurrence (R15 champion + all-thread poll + resident W_hi frags).
// grid 128 = 32 ng x 4 bg; CTA = 32 n x 16 b. 256 thr = 8 warps:
// warp = kg*2 + wn; kg owns k-chunk of 256, wn n-half of 16.
// ---------------------------------------------------------------------------
#define oWloB 66048u
#define oHhiB 132096u
#define oHloB 165120u
#define oRedB 198144u
#define oPreB 216576u
#define RNN_SMEM 220672

__global__ void __launch_bounds__(256) rnn_mma_k(const __nv_bfloat16* __restrict__ Whi,
                                                 const __nv_bfloat16* __restrict__ Wlo,
                                                 const float* __restrict__ pre,
                                                 __nv_bfloat16* Hhi,
                                                 __nv_bfloat16* Hlo,
                                                 int* __restrict__ flags) {
    extern __shared__ __align__(16) char sch[];
    const unsigned smb = smem_u32(sch);
    const int tid = threadIdx.x, lane = tid & 31, warp = tid >> 5;
    const int wn = warp & 1, kg = warp >> 1;
    const int bg = blockIdx.x & 3, ng = blockIdx.x >> 2;
    const int n0 = ng * 32, b0 = bg * 16;
    const int mychunk = ng >> 3;
    const int gtid = tid & 63;

    // Load W slice (rows with 1032-half stride)
    for (int i = tid; i < 32 * 128; i += 256) {
        int r = i >> 7, c = i & 127;
        cpasync16r(smb + (r * 1032 + c * 8) * 2, Whi + (size_t)(n0 + r) * H_ + c * 8);
        cpasync16r(smb + oWloB + (r * 1032 + c * 8) * 2, Wlo + (size_t)(n0 + r) * H_ + c * 8);
    }
    asm volatile("cp.async.wait_all;" ::: "memory");

    // t = 0: h_0 = tanh(pre_0), split-stored
    {
        int b = tid >> 4, P = tid & 15;
        float2 v = *(const float2*)(pre + ((size_t)(b0 + b)) * H_ + n0 + P * 2);
        u32 lo, hi = splitpk(tanhf(v.x), tanhf(v.y), lo);
        size_t o = ((size_t)(b0 + b)) * H_ + n0 + P * 2;
        *(u32*)(Hhi + o) = hi;
        *(u32*)(Hlo + o) = lo;
    }
    __syncwarp();
    if (lane == 0) red_release(&flags[0 * 16 + bg * 4 + mychunk]);
    __syncthreads();   // W slice visible to all warps

    const int arow = (lane & 7) + ((lane & 8) ? 8 : 0);
    const int acol = (lane & 16) ? 8 : 0;
    const int brow = wn * 16 + (lane & 7);
    const int bcol = (lane & 8) ? 8 : 0;

    // Resident W_hi fragments (static across all 512 steps): 16 ks x 2 n-groups
    u32 wh0[16][2], wh1[16][2];
#pragma unroll
    for (int ks = 0; ks < 16; ks++) {
        const int kk = kg * 256 + ks * 16;
        unsigned wb0 = smb + (brow * 1032 + kk + bcol) * 2;
        LDSM2(wh0[ks], wb0);
        LDSM2(wh1[ks], wb0 + 8 * 1032 * 2);
    }

    for (int t = 1; t < S_; t++) {
        float* redw = (float*)(sch + oRedB + (t & 1) * 9216);
        float* sPw  = (float*)(sch + oPreB + (t & 1) * 2048);

        // prefetch pre_t tile (512 floats)
        if (tid < 128) {
            int r = tid >> 3, c = (tid & 7) * 4;
            cpasync16r(smb + oPreB + (t & 1) * 2048 + (r * 32 + c) * 4,
                       pre + ((size_t)t * B_ + b0 + r) * H_ + n0 + c);
        }
        // all threads of this kg poll own chunk flag, then issue own copies
        {
            const int* fl = &flags[(t - 1) * 16 + bg * 4 + kg];
            while (ld_acq(fl) < 64) { }
        }
        // copy h chunk kg (hi+lo): 16 rows x 512B each half
        {
            const __nv_bfloat16* sh_ = Hhi + ((size_t)(t - 1) * B_ + b0) * H_ + kg * 256;
            const __nv_bfloat16* sl_ = Hlo + ((size_t)(t - 1) * B_ + b0) * H_ + kg * 256;
#pragma unroll
            for (int i = 0; i < 8; i++) {
                int v = gtid + i * 64, r = v >> 5, c = v & 31;
                unsigned so = ((r * 1032 + kg * 256 + c * 8)) * 2;
                cpasync16r(smb + oHhiB + so, sh_ + (size_t)r * H_ + c * 8);
                cpasync16r(smb + oHloB + so, sl_ + (size_t)r * H_ + c * 8);
            }
            asm volatile("cp.async.wait_all;" ::: "memory");
            asm volatile("bar.sync %0, 64;" :: "r"(1 + kg) : "memory");
        }

        // compute: 16b x 16n x 256k per warp, 3 split terms (W_hi resident)
        float c0[4] = {0, 0, 0, 0}, c1[4] = {0, 0, 0, 0};
#pragma unroll
        for (int ks = 0; ks < 16; ks++) {
            const int kk = kg * 256 + ks * 16;
            u32 ah[4], al[4], bl[2];
            unsigned aoff = (arow * 1032 + kk + acol) * 2;
            LDSM4(ah, smb + oHhiB + aoff);
            LDSM4(al, smb + oHloB + aoff);
            unsigned wb0 = smb + (brow * 1032 + kk + bcol) * 2;
            LDSM2(bl, wb0 + oWloB);
            MMA16816(c0, ah, wh0[ks][0], wh0[ks][1]);
            MMA16816(c0, ah, bl[0], bl[1]);
            MMA16816(c0, al, wh0[ks][0], wh0[ks][1]);
            LDSM2(bl, wb0 + 8 * 1032 * 2 + oWloB);
            MMA16816(c1, ah, wh1[ks][0], wh1[ks][1]);
            MMA16816(c1, ah, bl[0], bl[1]);
            MMA16816(c1, al, wh1[ks][0], wh1[ks][1]);
        }
        // write kg-partials: red[kg][b(16)][36]
        {
            int rb = lane >> 2, nb = wn * 16 + (lane & 3) * 2;
#pragma unroll
            for (int e = 0; e < 4; e++) {
                int b = rb + ((e >= 2) ? 8 : 0);
                int n = nb + (e & 1);
                redw[(kg * 16 + b) * 36 + n] = (e & 2) ? ((e & 1) ? c0[3] : c0[2])
                                                       : ((e & 1) ? c0[1] : c0[0]);
                redw[(kg * 16 + b) * 36 + n + 8] = (e & 2) ? ((e & 1) ? c1[3] : c1[2])
                                                           : ((e & 1) ? c1[1] : c1[0]);
            }
        }
        __syncthreads();

        // finalize: thread -> (b, n-pair)
        {
            int b = tid >> 4, P = tid & 15;
            float sx = 0.f, sy = 0.f;
#pragma unroll
            for (int g = 0; g < 4; g++) {
                sx += redw[(g * 16 + b) * 36 + P * 2];
                sy += redw[(g * 16 + b) * 36 + P * 2 + 1];
            }
            float2 pv = *(const float2*)(sPw + b * 32 + P * 2);
            u32 lo, hi = splitpk(tanhf(sx + pv.x), tanhf(sy + pv.y), lo);
            size_t o = ((size_t)t * B_ + b0 + b) * H_ + n0 + P * 2;
            *(u32*)(Hhi + o) = hi;
            *(u32*)(Hlo + o) = lo;
        }
        __syncwarp();
        if (lane == 0) red_release(&flags[t * 16 + bg * 4 + mychunk]);
    }
}

// ---------------------------------------------------------------------------

extern "C" void kernel_launch(void* const* d_in, const int* in_sizes, int n_in,
                              void* d_out, int out_size) {
    const float* x      = (const float*)d_in[0];
    const float* W_ih_0 = (const float*)d_in[1];
    const float* W_hh_0 = (const float*)d_in[2];
    const float* b_ih_0 = (const float*)d_in[3];
    const float* b_hh_0 = (const float*)d_in[4];
    const float* W_ih_1 = (const float*)d_in[5];
    const float* W_hh_1 = (const float*)d_in[6];
    const float* b_ih_1 = (const float*)d_in[7];
    const float* b_hh_1 = (const float*)d_in[8];
    const float* fc_w   = (const float*)d_in[9];
    const float* fc_b   = (const float*)d_in[10];
    float* out = (float*)d_out;

    float *buf0, *buf1;
    int* flags;
    __nv_bfloat16 *ahi, *alo, *bhi, *blo, *whi, *wlo;
    cudaGetSymbolAddress((void**)&buf0, g_buf0);
    cudaGetSymbolAddress((void**)&buf1, g_buf1);
    cudaGetSymbolAddress((void**)&flags, g_flags);
    cudaGetSymbolAddress((void**)&ahi, g_ahi);
    cudaGetSymbolAddress((void**)&alo, g_alo);
    cudaGetSymbolAddress((void**)&bhi, g_bhi);
    cudaGetSymbolAddress((void**)&blo, g_blo);
    cudaGetSymbolAddress((void**)&whi, g_whi);
    cudaGetSymbolAddress((void**)&wlo, g_wlo);

    const int mg_smem = 3 * STG_H * 2;   // 92160 B
    static bool attr_set = false;
    if (!attr_set) {
        cudaFuncSetAttribute(rnn_mma_k, cudaFuncAttributeMaxDynamicSharedMemorySize, RNN_SMEM);
        cudaFuncSetAttribute(mgemm_k<I_, 2, 1>, cudaFuncAttributeMaxDynamicSharedMemorySize, mg_smem);
        cudaFuncSetAttribute(mgemm_k<H_, 0, 1>, cudaFuncAttributeMaxDynamicSharedMemorySize, mg_smem);
        cudaFuncSetAttribute(mgemm_k<H_, 1, 0>, cudaFuncAttributeMaxDynamicSharedMemorySize, mg_smem);
        attr_set = true;
    }

    zero_flags_k<<<16, 1024>>>(flags);
    // pre0: split x and W_ih_0, tensor GEMM into buf0 [s][b][h]
    split_k<<<(B_ * S_ * I_ / 4) / 256, 256>>>(x, ahi, alo);
    split_k<<<(H_ * I_ / 4) / 256, 256>>>(W_ih_0, bhi, blo);
    mgemm_k<I_, 2, 1><<<dim3(H_ / 64, (B_ * S_) / 128), 256, mg_smem>>>(
        ahi, alo, bhi, blo, b_ih_0, b_hh_0, buf0);
    // L0 recurrence (writes h0 hi/lo into ahi/alo)
    split_k<<<(H_ * H_ / 4) / 256, 256>>>(W_hh_0, whi, wlo);
    rnn_mma_k<<<128, 256, RNN_SMEM>>>(whi, wlo, buf0, ahi, alo, flags);
    // pre1 = h0 @ W1_ih^T + biases (h0 already split)
    split_k<<<(H_ * H_ / 4) / 256, 256>>>(W_ih_1, bhi, blo);
    mgemm_k<H_, 0, 1><<<dim3(H_ / 64, (S_ * B_) / 128), 256, mg_smem>>>(
        ahi, alo, bhi, blo, b_ih_1, b_hh_1, buf1);
    // L1 recurrence (writes h1 hi/lo into ahi/alo)
    split_k<<<(H_ * H_ / 4) / 256, 256>>>(W_hh_1, whi, wlo);
    rnn_mma_k<<<128, 256, RNN_SMEM>>>(whi, wlo, buf1, ahi, alo, flags + S_ * 16);
    // fc (h1 already split)
    split_k<<<(O_ * H_ / 4) / 256, 256>>>(fc_w, bhi, blo);
    mgemm_k<H_, 1, 0><<<dim3(O_ / 64, (S_ * B_) / 128), 256, mg_smem>>>(
        ahi, alo, bhi, blo, fc_b, nullptr, out);
}